// round 1
// baseline (speedup 1.0000x reference)
#include <cuda_runtime.h>

#define N_NODES 2000
#define N_EDGES 32000
#define NG      320      // B*T graphs
#define OUTF    8
#define HID     24
#define BB      16
#define TT      20
#define NEG_SLOPE 0.2f

// ---------------- scratch (device globals; no allocs allowed) ----------------
__device__ float  g_wT[(size_t)N_EDGES * NG];   // [E][320]  transposed edge weights
__device__ float  g_xT[(size_t)N_NODES * NG];   // [N][320]  transposed node feats
__device__ int2   g_col[N_EDGES];               // CSR payload: (src, orig_edge_id)
__device__ int    g_rowptr[N_NODES + 1];
__device__ int    g_deg[N_NODES];
__device__ int    g_cur[N_NODES];
__device__ float2 g_S[NG];                      // per-graph (S1, S2)
__device__ float  g_hs[NG * HID];               // LSTM hidden outputs [320][24]

// ---------------- prep ----------------
__global__ void zero_kernel() {
    int i = blockIdx.x * blockDim.x + threadIdx.x;
    if (i < N_NODES) { g_deg[i] = 0; g_cur[i] = 0; }
    if (i < NG * 2)  { ((float*)g_S)[i] = 0.0f; }
}

__global__ void hist_kernel(const int* __restrict__ dst) {
    int e = blockIdx.x * blockDim.x + threadIdx.x;
    if (e < N_EDGES) atomicAdd(&g_deg[dst[e]], 1);
}

__global__ void scan_kernel() {
    __shared__ int sh[1024];
    int t = threadIdx.x;
    int a = (2 * t     < N_NODES) ? g_deg[2 * t]     : 0;
    int b = (2 * t + 1 < N_NODES) ? g_deg[2 * t + 1] : 0;
    int v = a + b;
    sh[t] = v;
    __syncthreads();
    for (int off = 1; off < 1024; off <<= 1) {
        int add = (t >= off) ? sh[t - off] : 0;
        __syncthreads();
        sh[t] += add;
        __syncthreads();
    }
    int incl = sh[t];
    int excl = incl - v;
    if (2 * t     < N_NODES) g_rowptr[2 * t]     = excl;
    if (2 * t + 1 < N_NODES) g_rowptr[2 * t + 1] = excl + a;
    if (t == 1023) g_rowptr[N_NODES] = incl;
}

__global__ void scatter_kernel(const int* __restrict__ src, const int* __restrict__ dst) {
    int e = blockIdx.x * blockDim.x + threadIdx.x;
    if (e < N_EDGES) {
        int d = dst[e];
        int pos = g_rowptr[d] + atomicAdd(&g_cur[d], 1);
        g_col[pos] = make_int2(src[e], e);
    }
}

// ---------------- transposes: [320][C] -> [C][320] ----------------
__global__ void transpose_w(const float* __restrict__ in) {
    __shared__ float tile[32][33];
    int cb = blockIdx.x * 32, rb = blockIdx.y * 32;
    int tx = threadIdx.x, ty = threadIdx.y;
    #pragma unroll
    for (int i = 0; i < 32; i += 8) {
        int r = rb + ty + i, c = cb + tx;
        tile[ty + i][tx] = in[(size_t)r * N_EDGES + c];
    }
    __syncthreads();
    #pragma unroll
    for (int i = 0; i < 32; i += 8) {
        int c = cb + ty + i, r = rb + tx;
        g_wT[(size_t)c * NG + r] = tile[tx][ty + i];
    }
}

__global__ void transpose_x(const float* __restrict__ in) {
    __shared__ float tile[32][33];
    int cb = blockIdx.x * 32, rb = blockIdx.y * 32;
    int tx = threadIdx.x, ty = threadIdx.y;
    #pragma unroll
    for (int i = 0; i < 32; i += 8) {
        int r = rb + ty + i, c = cb + tx;
        if (c < N_NODES) tile[ty + i][tx] = in[(size_t)r * N_NODES + c];
    }
    __syncthreads();
    #pragma unroll
    for (int i = 0; i < 32; i += 8) {
        int c = cb + ty + i, r = rb + tx;
        if (c < N_NODES) g_xT[(size_t)c * NG + r] = tile[tx][ty + i];
    }
}

// ---------------- main GAT reduction ----------------
// warp = (node, graph-group of 32); lane = graph within group.
// Single pass per edge: den += exp(e); T1 += exp(e)*x[src]; T2 += exp(e)*w;
// node contribution to graph sums = T1/den, T2/den.
__global__ void gat_kernel(const float* __restrict__ W_node,
                           const float* __restrict__ W_edge,
                           const float* __restrict__ attn_l,
                           const float* __restrict__ attn_e,
                           const float* __restrict__ attn_r) {
    int warp = (blockIdx.x * blockDim.x + threadIdx.x) >> 5;
    int lane = threadIdx.x & 31;
    if (warp >= N_NODES * (NG / 32)) return;
    int node = warp / (NG / 32);
    int gg   = warp % (NG / 32);
    int g    = gg * 32 + lane;

    float cL = 0.f, cE = 0.f, cR = 0.f;
    #pragma unroll
    for (int o = 0; o < OUTF; o++) {
        float wn = __ldg(&W_node[o]);
        float we = __ldg(&W_edge[o]);
        cL = fmaf(wn, __ldg(&attn_l[o]), cL);
        cR = fmaf(wn, __ldg(&attn_r[o]), cR);
        cE = fmaf(we, __ldg(&attn_e[o]), cE);
    }

    float xd = g_xT[(size_t)node * NG + g];
    float base_d = cR * xd;
    int s0 = g_rowptr[node], s1 = g_rowptr[node + 1];

    float den = 0.f, T1 = 0.f, T2 = 0.f;
    for (int j = s0; j < s1; j++) {
        int2 se = g_col[j];
        float w  = g_wT[(size_t)se.y * NG + g];
        float xs = g_xT[(size_t)se.x * NG + g];
        float ev = fmaf(cL, xs, fmaf(cE, w, base_d));
        ev = (ev > 0.f) ? ev : NEG_SLOPE * ev;
        float p = __expf(ev);
        den += p;
        T1 = fmaf(p, xs, T1);
        T2 = fmaf(p, w,  T2);
    }
    if (s1 > s0) {
        float inv = 1.0f / den;
        atomicAdd(&g_S[g].x, T1 * inv);
        atomicAdd(&g_S[g].y, T2 * inv);
    }
}

// ---------------- LSTM (one CTA per batch element) ----------------
__device__ __forceinline__ float sigm(float x) { return 1.0f / (1.0f + __expf(-x)); }

__global__ void lstm_kernel(const float* __restrict__ W_node,
                            const float* __restrict__ W_edge,
                            const float* __restrict__ gat_b,
                            const float* __restrict__ w_ih,
                            const float* __restrict__ w_hh,
                            const float* __restrict__ b_ih,
                            const float* __restrict__ b_hh) {
    int b = blockIdx.x;          // 0..15
    int tid = threadIdx.x;       // 128 threads
    __shared__ float h[HID], c[HID], gates[4 * HID], xt[OUTF];

    float wih[OUTF];
    float whh[HID];
    float bsum = 0.f;
    if (tid < 4 * HID) {
        #pragma unroll
        for (int k = 0; k < OUTF; k++) wih[k] = w_ih[tid * OUTF + k];
        #pragma unroll
        for (int j = 0; j < HID; j++) whh[j] = w_hh[tid * HID + j];
        bsum = b_ih[tid] + b_hh[tid];
    }
    if (tid < HID) { h[tid] = 0.f; c[tid] = 0.f; }
    __syncthreads();

    for (int t = 0; t < TT; t++) {
        if (tid < OUTF) {
            int gid = b * TT + t;
            float2 S = g_S[gid];
            xt[tid] = fmaf(S.x, W_node[tid], S.y * W_edge[tid]) * (1.0f / N_NODES) + gat_b[tid];
        }
        __syncthreads();
        if (tid < 4 * HID) {
            float acc = bsum;
            #pragma unroll
            for (int k = 0; k < OUTF; k++) acc = fmaf(wih[k], xt[k], acc);
            #pragma unroll
            for (int j = 0; j < HID; j++) acc = fmaf(whh[j], h[j], acc);
            gates[tid] = acc;
        }
        __syncthreads();
        if (tid < HID) {
            float gi = sigm(gates[tid]);
            float gf = sigm(gates[HID + tid]);
            float gc = tanhf(gates[2 * HID + tid]);
            float go = sigm(gates[3 * HID + tid]);
            float cn = fmaf(gf, c[tid], gi * gc);
            c[tid] = cn;
            float hn = go * tanhf(cn);
            h[tid] = hn;
            g_hs[(b * TT + t) * HID + tid] = hn;
        }
        __syncthreads();
    }
}

// ---------------- fc + fcc head (one CTA per row) ----------------
__global__ void fc_kernel(const float* __restrict__ fc_w,
                          const float* __restrict__ fc_b,
                          const float* __restrict__ fcc_w,
                          const float* __restrict__ fcc_b,
                          float* __restrict__ out) {
    int r = blockIdx.x;          // 0..319
    int m = threadIdx.x;         // 160 threads
    __shared__ float fcv[160];
    __shared__ float hrow[HID];
    if (m < HID) hrow[m] = g_hs[r * HID + m];
    __syncthreads();
    float acc = fc_b[m];
    #pragma unroll
    for (int k = 0; k < HID; k++) acc = fmaf(hrow[k], fc_w[m * HID + k], acc);
    fcv[m] = acc;
    __syncthreads();
    if (m < 20) {
        float a2 = fcc_b[m];
        #pragma unroll 8
        for (int q = 0; q < 160; q++) a2 = fmaf(fcv[q], fcc_w[m * 160 + q], a2);
        out[r * 20 + m] = a2;
    }
}

// ---------------- launch ----------------
extern "C" void kernel_launch(void* const* d_in, const int* in_sizes, int n_in,
                              void* d_out, int out_size) {
    const float* x      = (const float*)d_in[0];
    const float* ew     = (const float*)d_in[1];
    const int*   src    = (const int*)  d_in[2];
    const int*   dst    = (const int*)  d_in[3];
    const float* W_node = (const float*)d_in[4];
    const float* W_edge = (const float*)d_in[5];
    const float* attn_l = (const float*)d_in[6];
    const float* attn_e = (const float*)d_in[7];
    const float* attn_r = (const float*)d_in[8];
    const float* gat_b  = (const float*)d_in[9];
    const float* w_ih   = (const float*)d_in[10];
    const float* w_hh   = (const float*)d_in[11];
    const float* b_ih   = (const float*)d_in[12];
    const float* b_hh   = (const float*)d_in[13];
    const float* fc_w   = (const float*)d_in[14];
    const float* fc_b   = (const float*)d_in[15];
    const float* fcc_w  = (const float*)d_in[16];
    const float* fcc_b  = (const float*)d_in[17];
    float* out = (float*)d_out;

    zero_kernel<<<16, 256>>>();
    hist_kernel<<<(N_EDGES + 255) / 256, 256>>>(dst);
    scan_kernel<<<1, 1024>>>();
    scatter_kernel<<<(N_EDGES + 255) / 256, 256>>>(src, dst);

    transpose_w<<<dim3(N_EDGES / 32, NG / 32), dim3(32, 8)>>>(ew);
    transpose_x<<<dim3((N_NODES + 31) / 32, NG / 32), dim3(32, 8)>>>(x);

    // 2000 nodes * 10 graph-groups = 20000 warps; 8 warps/CTA -> 2500 CTAs
    gat_kernel<<<2500, 256>>>(W_node, W_edge, attn_l, attn_e, attn_r);

    lstm_kernel<<<BB, 128>>>(W_node, W_edge, gat_b, w_ih, w_hh, b_ih, b_hh);
    fc_kernel<<<NG, 160>>>(fc_w, fc_b, fcc_w, fcc_b, out);
}